// round 1
// baseline (speedup 1.0000x reference)
#include <cuda_runtime.h>
#include <cstdint>

#define NTOK    49
#define NHEADS  16
#define HDIM    32
#define DIMC    512
#define BATCH   2048
#define NWIN    64
#define QK_SCALE 0.17677669529663687f   // 32^-0.5

// ---------------- scratch (device globals: allocation-free) ----------------
// qkv: (2048*49, 1536) fp32
__device__ float g_qkv[(size_t)BATCH * NTOK * 3 * DIMC];
// attention output in (m, 512) layout, m = b*49+n, col = h*32+d
__device__ float g_obuf[(size_t)BATCH * NTOK * DIMC];

// ---------------- TF32 GEMM: C[M,N] = A[M,512] * B[N,512]^T + bias[N] -----
// Block tile 128x128, BK=32, 256 threads = 8 warps (4 m x 2 n), warp tile 32x64.
// Double-buffered cp.async. Smem pad 36 floats/row -> conflict-free mma frag LDS.

#define BK  32
#define PAD 36
#define STAGE_F (128 * PAD)       // floats per matrix per stage

__device__ __forceinline__ uint32_t f2tf(float f) {
    uint32_t u;
    asm volatile("cvt.rna.tf32.f32 %0, %1;" : "=r"(u) : "f"(f));
    return u;
}

__global__ __launch_bounds__(256, 2)
void gemm_tf32(const float* __restrict__ A, const float* __restrict__ B,
               const float* __restrict__ bias, float* __restrict__ C, int N)
{
    extern __shared__ float sm[];
    float* As = sm;                    // 2 stages * 128*PAD
    float* Bs = sm + 2 * STAGE_F;

    const int tid  = threadIdx.x;
    const int warp = tid >> 5, lane = tid & 31;
    const int wm   = warp & 3, wn = warp >> 2;   // warp origin (wm*32, wn*64)
    const int grp  = lane >> 2, tig = lane & 3;

    const long rowA0 = (long)blockIdx.y * 128;
    const long rowB0 = (long)blockIdx.x * 128;

    const int lrow = tid >> 3;          // 0..31
    const int lcol = (tid & 7) * 4;     // 0..28 step 4

    float acc[2][8][4];
    #pragma unroll
    for (int i = 0; i < 2; i++)
        #pragma unroll
        for (int j = 0; j < 8; j++)
            #pragma unroll
            for (int q = 0; q < 4; q++) acc[i][j][q] = 0.f;

    auto issue = [&](int stage, int kt) {
        const float* ga = A + rowA0 * DIMC + kt * BK;
        const float* gb = B + rowB0 * DIMC + kt * BK;
        float* sa = As + stage * STAGE_F;
        float* sb = Bs + stage * STAGE_F;
        #pragma unroll
        for (int it = 0; it < 4; it++) {
            int r = lrow + it * 32;
            uint32_t da = (uint32_t)__cvta_generic_to_shared(sa + r * PAD + lcol);
            asm volatile("cp.async.cg.shared.global [%0], [%1], 16;\n"
                         :: "r"(da), "l"(ga + (long)r * DIMC + lcol));
            uint32_t db = (uint32_t)__cvta_generic_to_shared(sb + r * PAD + lcol);
            asm volatile("cp.async.cg.shared.global [%0], [%1], 16;\n"
                         :: "r"(db), "l"(gb + (long)r * DIMC + lcol));
        }
        asm volatile("cp.async.commit_group;\n");
    };

    issue(0, 0);
    const int NK = DIMC / BK;   // 16

    for (int kt = 0; kt < NK; kt++) {
        int stage = kt & 1;
        if (kt + 1 < NK) {
            issue(stage ^ 1, kt + 1);
            asm volatile("cp.async.wait_group 1;\n");
        } else {
            asm volatile("cp.async.wait_group 0;\n");
        }
        __syncthreads();

        const float* sa = As + stage * STAGE_F + wm * 32 * PAD;
        const float* sb = Bs + stage * STAGE_F + wn * 64 * PAD;

        #pragma unroll
        for (int k8 = 0; k8 < BK / 8; k8++) {
            uint32_t afr[2][4], bfr[8][2];
            #pragma unroll
            for (int mi = 0; mi < 2; mi++) {
                const float* p = sa + (mi * 16 + grp) * PAD + k8 * 8 + tig;
                afr[mi][0] = f2tf(p[0]);
                afr[mi][1] = f2tf(p[8 * PAD]);
                afr[mi][2] = f2tf(p[4]);
                afr[mi][3] = f2tf(p[8 * PAD + 4]);
            }
            #pragma unroll
            for (int ni = 0; ni < 8; ni++) {
                const float* p = sb + (ni * 8 + grp) * PAD + k8 * 8 + tig;
                bfr[ni][0] = f2tf(p[0]);
                bfr[ni][1] = f2tf(p[4]);
            }
            #pragma unroll
            for (int mi = 0; mi < 2; mi++)
                #pragma unroll
                for (int ni = 0; ni < 8; ni++) {
                    asm volatile(
                        "mma.sync.aligned.m16n8k8.row.col.f32.tf32.tf32.f32 "
                        "{%0,%1,%2,%3}, {%4,%5,%6,%7}, {%8,%9}, {%0,%1,%2,%3};\n"
                        : "+f"(acc[mi][ni][0]), "+f"(acc[mi][ni][1]),
                          "+f"(acc[mi][ni][2]), "+f"(acc[mi][ni][3])
                        : "r"(afr[mi][0]), "r"(afr[mi][1]),
                          "r"(afr[mi][2]), "r"(afr[mi][3]),
                          "r"(bfr[ni][0]), "r"(bfr[ni][1]));
                }
        }
        __syncthreads();
    }

    // epilogue: +bias, float2 stores
    #pragma unroll
    for (int mi = 0; mi < 2; mi++) {
        long r0 = rowA0 + wm * 32 + mi * 16 + grp;
        #pragma unroll
        for (int ni = 0; ni < 8; ni++) {
            long c = rowB0 + wn * 64 + ni * 8 + tig * 2;
            float b0 = bias[c], b1 = bias[c + 1];
            float2 v0 = make_float2(acc[mi][ni][0] + b0, acc[mi][ni][1] + b1);
            float2 v1 = make_float2(acc[mi][ni][2] + b0, acc[mi][ni][3] + b1);
            *(float2*)(C + r0 * N + c)       = v0;
            *(float2*)(C + (r0 + 8) * N + c) = v1;
        }
    }
}

// ---------------- fused window attention: one block per (b, h) ------------
__global__ __launch_bounds__(128)
void attn_kernel(const float* __restrict__ qkv, const float* __restrict__ mask,
                 const float* __restrict__ rpb, float* __restrict__ obuf)
{
    __shared__ float qs[NTOK * 33], ks[NTOK * 33], vs[NTOK * 33];
    __shared__ float as_[NTOK * 50];

    const int h = blockIdx.x, b = blockIdx.y;
    const int tid = threadIdx.x;

    // load q,k,v (49 x 32 each); q pre-scaled
    const long base = (long)b * NTOK * (3 * DIMC) + h * HDIM;
    for (int idx = tid; idx < NTOK * HDIM; idx += 128) {
        int n = idx >> 5, d = idx & 31;
        const float* p = qkv + base + (long)n * (3 * DIMC) + d;
        qs[n * 33 + d] = p[0] * QK_SCALE;
        ks[n * 33 + d] = p[DIMC];
        vs[n * 33 + d] = p[2 * DIMC];
    }
    __syncthreads();

    // S = q k^T + bias(rel pos) + mask(window)
    const int w = b & (NWIN - 1);
    for (int idx = tid; idx < NTOK * NTOK; idx += 128) {
        int i = idx / NTOK, j = idx - i * NTOK;
        float s = 0.f;
        #pragma unroll
        for (int d = 0; d < HDIM; d++) s += qs[i * 33 + d] * ks[j * 33 + d];
        int ih = i / 7, iw = i - ih * 7;
        int jh = j / 7, jw = j - jh * 7;
        int ridx = (ih - jh + 6) * 13 + (iw - jw + 6);
        s += rpb[ridx * NHEADS + h];
        s += mask[((long)w * NTOK + i) * NTOK + j];
        as_[i * 50 + j] = s;
    }
    __syncthreads();

    // exact softmax per row (49 rows)
    if (tid < NTOK) {
        float m = -1e30f;
        #pragma unroll
        for (int j = 0; j < NTOK; j++) m = fmaxf(m, as_[tid * 50 + j]);
        float sum = 0.f;
        #pragma unroll
        for (int j = 0; j < NTOK; j++) {
            float e = expf(as_[tid * 50 + j] - m);
            as_[tid * 50 + j] = e;
            sum += e;
        }
        float inv = 1.f / sum;
        #pragma unroll
        for (int j = 0; j < NTOK; j++) as_[tid * 50 + j] *= inv;
    }
    __syncthreads();

    // O = attn * V, write (m, 512) layout for proj GEMM
    for (int idx = tid; idx < NTOK * HDIM; idx += 128) {
        int i = idx >> 5, d = idx & 31;
        float s = 0.f;
        #pragma unroll
        for (int j = 0; j < NTOK; j++) s += as_[i * 50 + j] * vs[j * 33 + d];
        obuf[((long)b * NTOK + i) * DIMC + h * HDIM + d] = s;
    }
}

// ---------------- launch ---------------------------------------------------
extern "C" void kernel_launch(void* const* d_in, const int* in_sizes, int n_in,
                              void* d_out, int out_size)
{
    const float* x      = (const float*)d_in[0];
    const float* mask   = (const float*)d_in[1];
    const float* qkv_w  = (const float*)d_in[2];
    const float* qkv_b  = (const float*)d_in[3];
    const float* proj_w = (const float*)d_in[4];
    const float* proj_b = (const float*)d_in[5];
    const float* rpb    = (const float*)d_in[6];
    float* out = (float*)d_out;

    float *qkvbuf = nullptr, *obuf = nullptr;
    cudaGetSymbolAddress((void**)&qkvbuf, g_qkv);
    cudaGetSymbolAddress((void**)&obuf,  g_obuf);

    const int SMEM = 2 * 2 * 128 * PAD * 4;   // 73728 bytes
    cudaFuncSetAttribute(gemm_tf32, cudaFuncAttributeMaxDynamicSharedMemorySize, SMEM);

    const int M = BATCH * NTOK;               // 100352

    // 1) qkv = x @ qkv_w^T + qkv_b      (M x 1536)
    dim3 g1(3 * DIMC / 128, M / 128);
    gemm_tf32<<<g1, 256, SMEM>>>(x, qkv_w, qkv_b, qkvbuf, 3 * DIMC);

    // 2) windowed attention
    attn_kernel<<<dim3(NHEADS, BATCH), 128>>>(qkvbuf, mask, rpb, obuf);

    // 3) out = attn_out @ proj_w^T + proj_b   (M x 512)
    dim3 g2(DIMC / 128, M / 128);
    gemm_tf32<<<g2, 256, SMEM>>>(obuf, proj_w, proj_b, out, DIMC);
}

// round 3
// speedup vs baseline: 1.2572x; 1.2572x over previous
#include <cuda_runtime.h>
#include <cuda_fp16.h>
#include <cstdint>

#define NTOK    49
#define NHEADS  16
#define HDIM    32
#define DIMC    512
#define BATCH   2048
#define NWIN    64
#define QK_SCALE 0.17677669529663687f   // 32^-0.5
#define M_TOT   (BATCH * NTOK)          // 100352

// ---------------- scratch (device globals: allocation-free) ----------------
__device__ float  g_qkv [(size_t)M_TOT * 3 * DIMC];   // (M, 1536) fp32
__device__ __half g_obuf[(size_t)M_TOT * DIMC];       // (M, 512)  fp16
__device__ __half g_xh  [(size_t)M_TOT * DIMC];       // x in fp16
__device__ __half g_wqkv[(size_t)3 * DIMC * DIMC];    // qkv_w fp16
__device__ __half g_wprj[(size_t)DIMC * DIMC];        // proj_w fp16

// ---------------- fp32 -> fp16 convert (vectorized) ------------------------
__global__ void f2h_kernel(const float* __restrict__ in, __half* __restrict__ out, long n4)
{
    long i = (long)blockIdx.x * blockDim.x + threadIdx.x;
    if (i >= n4) return;
    float4 v = ((const float4*)in)[i];
    __half2 h0 = __floats2half2_rn(v.x, v.y);
    __half2 h1 = __floats2half2_rn(v.z, v.w);
    uint2 p;
    p.x = *(uint32_t*)&h0;
    p.y = *(uint32_t*)&h1;
    ((uint2*)out)[i] = p;
}

// ============================================================================
// FP16 GEMM (fp32 accum): C[M,N] = A[M,512] * B[N,512]^T + bias[N]
// Block tile 128x128, BK=32, 256 threads = 8 warps (4m x 2n), warp tile 32x64.
// 3-stage cp.async. Smem rows padded to 80B -> conflict-free fragment LDS.
// ============================================================================

#define BK      32
#define ROWH    40                    // halves per padded row (80 B)
#define STAGE_H (128 * ROWH)          // halves per matrix per stage
#define NSTAGE  3
#define SMEM_GEMM (NSTAGE * 2 * STAGE_H * 2)   // bytes = 61440

__global__ __launch_bounds__(256, 2)
void gemm_hf(const __half* __restrict__ A, const __half* __restrict__ B,
             const float* __restrict__ bias, float* __restrict__ C, int N)
{
    extern __shared__ __half sm[];
    __half* As = sm;                          // NSTAGE * STAGE_H
    __half* Bs = sm + NSTAGE * STAGE_H;

    const int tid  = threadIdx.x;
    const int warp = tid >> 5, lane = tid & 31;
    const int wm   = warp & 3, wn = warp >> 2;    // warp origin (wm*32, wn*64)
    const int grp  = lane >> 2, tig = lane & 3;

    const long rowA0 = (long)blockIdx.y * 128;
    const long rowB0 = (long)blockIdx.x * 128;

    float acc[2][8][4];
    #pragma unroll
    for (int i = 0; i < 2; i++)
        #pragma unroll
        for (int j = 0; j < 8; j++)
            #pragma unroll
            for (int q = 0; q < 4; q++) acc[i][j][q] = 0.f;

    // stage fill: per matrix 128 rows x 64B = 512 x 16B chunks; 2 chunks/thread
    auto issue = [&](int s, int kt) {
        const __half* ga = A + rowA0 * DIMC + kt * BK;
        const __half* gb = B + rowB0 * DIMC + kt * BK;
        __half* sa = As + s * STAGE_H;
        __half* sb = Bs + s * STAGE_H;
        #pragma unroll
        for (int i = 0; i < 2; i++) {
            int q = tid + 256 * i;            // 0..511
            int r = q >> 2;                   // row 0..127
            int c = (q & 3) * 8;              // half offset 0,8,16,24
            uint32_t da = (uint32_t)__cvta_generic_to_shared(sa + r * ROWH + c);
            asm volatile("cp.async.cg.shared.global [%0], [%1], 16;\n"
                         :: "r"(da), "l"(ga + (long)r * DIMC + c));
            uint32_t db = (uint32_t)__cvta_generic_to_shared(sb + r * ROWH + c);
            asm volatile("cp.async.cg.shared.global [%0], [%1], 16;\n"
                         :: "r"(db), "l"(gb + (long)r * DIMC + c));
        }
        asm volatile("cp.async.commit_group;\n");
    };

    const int NK = DIMC / BK;   // 16
    issue(0, 0);
    issue(1, 1);

    for (int kt = 0; kt < NK; kt++) {
        const int s = kt % NSTAGE;
        if (kt + 2 < NK) {
            issue((kt + 2) % NSTAGE, kt + 2);
            asm volatile("cp.async.wait_group 2;\n");
        } else if (kt + 1 < NK) {
            asm volatile("cp.async.wait_group 1;\n");
        } else {
            asm volatile("cp.async.wait_group 0;\n");
        }
        __syncthreads();

        const __half* sa = As + s * STAGE_H + (wm * 32) * ROWH;
        const __half* sb = Bs + s * STAGE_H + (wn * 64) * ROWH;

        #pragma unroll
        for (int kk = 0; kk < BK / 16; kk++) {       // 2 k16 steps
            const int kc = kk * 16 + tig * 2;
            uint32_t afr[2][4], bfr[8][2];
            #pragma unroll
            for (int mi = 0; mi < 2; mi++) {
                const __half* p = sa + (mi * 16 + grp) * ROWH + kc;
                afr[mi][0] = *(const uint32_t*)(p);
                afr[mi][1] = *(const uint32_t*)(p + 8 * ROWH);
                afr[mi][2] = *(const uint32_t*)(p + 8);
                afr[mi][3] = *(const uint32_t*)(p + 8 * ROWH + 8);
            }
            #pragma unroll
            for (int ni = 0; ni < 8; ni++) {
                const __half* p = sb + (ni * 8 + grp) * ROWH + kc;
                bfr[ni][0] = *(const uint32_t*)(p);
                bfr[ni][1] = *(const uint32_t*)(p + 8);
            }
            #pragma unroll
            for (int mi = 0; mi < 2; mi++)
                #pragma unroll
                for (int ni = 0; ni < 8; ni++) {
                    asm volatile(
                        "mma.sync.aligned.m16n8k16.row.col.f32.f16.f16.f32 "
                        "{%0,%1,%2,%3}, {%4,%5,%6,%7}, {%8,%9}, {%0,%1,%2,%3};\n"
                        : "+f"(acc[mi][ni][0]), "+f"(acc[mi][ni][1]),
                          "+f"(acc[mi][ni][2]), "+f"(acc[mi][ni][3])
                        : "r"(afr[mi][0]), "r"(afr[mi][1]),
                          "r"(afr[mi][2]), "r"(afr[mi][3]),
                          "r"(bfr[ni][0]), "r"(bfr[ni][1]));
                }
        }
        __syncthreads();
    }

    // epilogue: +bias, float2 stores
    #pragma unroll
    for (int mi = 0; mi < 2; mi++) {
        long r0 = rowA0 + wm * 32 + mi * 16 + grp;
        #pragma unroll
        for (int ni = 0; ni < 8; ni++) {
            long c = rowB0 + wn * 64 + ni * 8 + tig * 2;
            float b0 = bias[c], b1 = bias[c + 1];
            float2 v0 = make_float2(acc[mi][ni][0] + b0, acc[mi][ni][1] + b1);
            float2 v1 = make_float2(acc[mi][ni][2] + b0, acc[mi][ni][3] + b1);
            *(float2*)(C + r0 * N + c)       = v0;
            *(float2*)(C + (r0 + 8) * N + c) = v1;
        }
    }
}

// ---------------- fused window attention: one block per (b, h) ------------
__global__ __launch_bounds__(128)
void attn_kernel(const float* __restrict__ qkv, const float* __restrict__ mask,
                 const float* __restrict__ rpb, __half* __restrict__ obuf)
{
    __shared__ float qs[NTOK * 33], ks[NTOK * 33], vs[NTOK * 33];
    __shared__ float as_[NTOK * 50];

    const int h = blockIdx.x, b = blockIdx.y;
    const int tid = threadIdx.x;

    const long base = (long)b * NTOK * (3 * DIMC) + h * HDIM;
    for (int idx = tid; idx < NTOK * HDIM; idx += 128) {
        int n = idx >> 5, d = idx & 31;
        const float* p = qkv + base + (long)n * (3 * DIMC) + d;
        qs[n * 33 + d] = p[0] * QK_SCALE;
        ks[n * 33 + d] = p[DIMC];
        vs[n * 33 + d] = p[2 * DIMC];
    }
    __syncthreads();

    const int w = b & (NWIN - 1);
    for (int idx = tid; idx < NTOK * NTOK; idx += 128) {
        int i = idx / NTOK, j = idx - i * NTOK;
        float s = 0.f;
        #pragma unroll
        for (int d = 0; d < HDIM; d++) s += qs[i * 33 + d] * ks[j * 33 + d];
        int ih = i / 7, iw = i - ih * 7;
        int jh = j / 7, jw = j - jh * 7;
        int ridx = (ih - jh + 6) * 13 + (iw - jw + 6);
        s += rpb[ridx * NHEADS + h];
        s += mask[((long)w * NTOK + i) * NTOK + j];
        as_[i * 50 + j] = s;
    }
    __syncthreads();

    if (tid < NTOK) {
        float m = -1e30f;
        #pragma unroll
        for (int j = 0; j < NTOK; j++) m = fmaxf(m, as_[tid * 50 + j]);
        float sum = 0.f;
        #pragma unroll
        for (int j = 0; j < NTOK; j++) {
            float e = expf(as_[tid * 50 + j] - m);
            as_[tid * 50 + j] = e;
            sum += e;
        }
        float inv = 1.f / sum;
        #pragma unroll
        for (int j = 0; j < NTOK; j++) as_[tid * 50 + j] *= inv;
    }
    __syncthreads();

    for (int idx = tid; idx < NTOK * HDIM; idx += 128) {
        int i = idx >> 5, d = idx & 31;
        float s = 0.f;
        #pragma unroll
        for (int j = 0; j < NTOK; j++) s += as_[i * 50 + j] * vs[j * 33 + d];
        obuf[((long)b * NTOK + i) * DIMC + h * HDIM + d] = __float2half_rn(s);
    }
}

// ---------------- launch ---------------------------------------------------
extern "C" void kernel_launch(void* const* d_in, const int* in_sizes, int n_in,
                              void* d_out, int out_size)
{
    const float* x      = (const float*)d_in[0];
    const float* mask   = (const float*)d_in[1];
    const float* qkv_w  = (const float*)d_in[2];
    const float* qkv_b  = (const float*)d_in[3];
    const float* proj_w = (const float*)d_in[4];
    const float* proj_b = (const float*)d_in[5];
    const float* rpb    = (const float*)d_in[6];
    float* out = (float*)d_out;

    float  *qkvbuf = nullptr;
    __half *obuf = nullptr, *xh = nullptr, *wqkv = nullptr, *wprj = nullptr;
    cudaGetSymbolAddress((void**)&qkvbuf, g_qkv);
    cudaGetSymbolAddress((void**)&obuf,  g_obuf);
    cudaGetSymbolAddress((void**)&xh,    g_xh);
    cudaGetSymbolAddress((void**)&wqkv,  g_wqkv);
    cudaGetSymbolAddress((void**)&wprj,  g_wprj);

    cudaFuncSetAttribute(gemm_hf, cudaFuncAttributeMaxDynamicSharedMemorySize, SMEM_GEMM);

    // 0) fp32 -> fp16 converts
    {
        long n4 = (long)M_TOT * DIMC / 4;
        f2h_kernel<<<(unsigned)((n4 + 255) / 256), 256>>>(x, xh, n4);
        long w4 = (long)3 * DIMC * DIMC / 4;
        f2h_kernel<<<(unsigned)((w4 + 255) / 256), 256>>>(qkv_w, wqkv, w4);
        long p4 = (long)DIMC * DIMC / 4;
        f2h_kernel<<<(unsigned)((p4 + 255) / 256), 256>>>(proj_w, wprj, p4);
    }

    // 1) qkv = x @ qkv_w^T + qkv_b      (M x 1536)
    dim3 g1(3 * DIMC / 128, M_TOT / 128);
    gemm_hf<<<g1, 256, SMEM_GEMM>>>(xh, wqkv, qkv_b, qkvbuf, 3 * DIMC);

    // 2) windowed attention (writes fp16 obuf)
    attn_kernel<<<dim3(NHEADS, BATCH), 128>>>(qkvbuf, mask, rpb, obuf);

    // 3) out = attn_out @ proj_w^T + proj_b   (M x 512)
    dim3 g2(DIMC / 128, M_TOT / 128);
    gemm_hf<<<g2, 256, SMEM_GEMM>>>(obuf, wprj, proj_b, out, DIMC);
}

// round 4
// speedup vs baseline: 2.4289x; 1.9320x over previous
#include <cuda_runtime.h>
#include <cuda_fp16.h>
#include <cstdint>

#define NTOK    49
#define NHEADS  16
#define HDIM    32
#define DIMC    512
#define BATCH   2048
#define NWIN    64
#define QK_SCALE 0.17677669529663687f   // 32^-0.5
#define M_TOT   (BATCH * NTOK)          // 100352

// ---------------- scratch (device globals: allocation-free) ----------------
__device__ __half g_qkvh[(size_t)M_TOT * 3 * DIMC];   // (M, 1536) fp16
__device__ __half g_obuf[(size_t)M_TOT * DIMC];       // (M, 512)  fp16
__device__ __half g_xh  [(size_t)M_TOT * DIMC];       // x in fp16
__device__ __half g_wqkv[(size_t)3 * DIMC * DIMC];    // qkv_w fp16
__device__ __half g_wprj[(size_t)DIMC * DIMC];        // proj_w fp16

// ---------------- helpers ---------------------------------------------------
__device__ __forceinline__ uint32_t sptr(const void* p) {
    return (uint32_t)__cvta_generic_to_shared(p);
}
__device__ __forceinline__ void ldsm4(uint32_t* r, uint32_t a) {
    asm volatile("ldmatrix.sync.aligned.m8n8.x4.shared.b16 {%0,%1,%2,%3}, [%4];"
                 : "=r"(r[0]), "=r"(r[1]), "=r"(r[2]), "=r"(r[3]) : "r"(a));
}
__device__ __forceinline__ void ldsm4t(uint32_t* r, uint32_t a) {
    asm volatile("ldmatrix.sync.aligned.m8n8.x4.trans.shared.b16 {%0,%1,%2,%3}, [%4];"
                 : "=r"(r[0]), "=r"(r[1]), "=r"(r[2]), "=r"(r[3]) : "r"(a));
}
__device__ __forceinline__ void mma16816(float* c, const uint32_t* a, const uint32_t* b) {
    asm volatile(
        "mma.sync.aligned.m16n8k16.row.col.f32.f16.f16.f32 "
        "{%0,%1,%2,%3}, {%4,%5,%6,%7}, {%8,%9}, {%0,%1,%2,%3};\n"
        : "+f"(c[0]), "+f"(c[1]), "+f"(c[2]), "+f"(c[3])
        : "r"(a[0]), "r"(a[1]), "r"(a[2]), "r"(a[3]), "r"(b[0]), "r"(b[1]));
}
__device__ __forceinline__ uint32_t packh2(float lo, float hi) {
    __half2 h = __floats2half2_rn(lo, hi);
    return *(uint32_t*)&h;
}

// ---------------- fp32 -> fp16 convert (vectorized) ------------------------
__global__ void f2h_kernel(const float* __restrict__ in, __half* __restrict__ out, long n4)
{
    long i = (long)blockIdx.x * blockDim.x + threadIdx.x;
    if (i >= n4) return;
    float4 v = ((const float4*)in)[i];
    uint2 p;
    p.x = packh2(v.x, v.y);
    p.y = packh2(v.z, v.w);
    ((uint2*)out)[i] = p;
}

// ============================================================================
// FP16 GEMM (fp32 accum): C[M,N] = A[M,512] * B[N,512]^T + bias[N]
// Block tile 128x128, BK=32, 256 threads = 8 warps (4m x 2n), warp tile 32x64.
// 3-stage cp.async, ldmatrix fragment loads (80B padded rows, conflict-free).
// ============================================================================

#define BK      32
#define ROWH    40                    // halves per padded row (80 B)
#define STAGE_H (128 * ROWH)
#define NSTAGE  3
#define SMEM_GEMM (NSTAGE * 2 * STAGE_H * 2)   // 61440 B

template<class OutT>
__global__ __launch_bounds__(256, 2)
void gemm_hf(const __half* __restrict__ A, const __half* __restrict__ B,
             const float* __restrict__ bias, OutT* __restrict__ C, int N)
{
    extern __shared__ __half sm[];
    __half* As = sm;
    __half* Bs = sm + NSTAGE * STAGE_H;

    const int tid  = threadIdx.x;
    const int warp = tid >> 5, lane = tid & 31;
    const int wm   = warp & 3, wn = warp >> 2;
    const int grp  = lane >> 2, tig = lane & 3;

    const long rowA0 = (long)blockIdx.y * 128;
    const long rowB0 = (long)blockIdx.x * 128;

    float acc[2][8][4];
    #pragma unroll
    for (int i = 0; i < 2; i++)
        #pragma unroll
        for (int j = 0; j < 8; j++)
            #pragma unroll
            for (int q = 0; q < 4; q++) acc[i][j][q] = 0.f;

    auto issue = [&](int s, int kt) {
        const __half* ga = A + rowA0 * DIMC + kt * BK;
        const __half* gb = B + rowB0 * DIMC + kt * BK;
        __half* sa = As + s * STAGE_H;
        __half* sb = Bs + s * STAGE_H;
        #pragma unroll
        for (int i = 0; i < 2; i++) {
            int q = tid + 256 * i;
            int r = q >> 2;
            int c = (q & 3) * 8;
            uint32_t da = sptr(sa + r * ROWH + c);
            asm volatile("cp.async.cg.shared.global [%0], [%1], 16;\n"
                         :: "r"(da), "l"(ga + (long)r * DIMC + c));
            uint32_t db = sptr(sb + r * ROWH + c);
            asm volatile("cp.async.cg.shared.global [%0], [%1], 16;\n"
                         :: "r"(db), "l"(gb + (long)r * DIMC + c));
        }
        asm volatile("cp.async.commit_group;\n");
    };

    const int NK = DIMC / BK;   // 16
    issue(0, 0);
    issue(1, 1);

    // per-lane ldmatrix row/col offsets
    const int aRow = ((lane >> 3) & 1) * 8 + (lane & 7);
    const int aCol = ((lane >> 4) & 1) * 8;
    const int bRow = ((lane >> 4) & 1) * 8 + (lane & 7);
    const int bCol = ((lane >> 3) & 1) * 8;

    for (int kt = 0; kt < NK; kt++) {
        const int s = kt % NSTAGE;
        if (kt + 2 < NK) {
            issue((kt + 2) % NSTAGE, kt + 2);
            asm volatile("cp.async.wait_group 2;\n");
        } else if (kt + 1 < NK) {
            asm volatile("cp.async.wait_group 1;\n");
        } else {
            asm volatile("cp.async.wait_group 0;\n");
        }
        __syncthreads();

        const __half* sa = As + s * STAGE_H;
        const __half* sb = Bs + s * STAGE_H;

        #pragma unroll
        for (int kk = 0; kk < 2; kk++) {
            const int kc = kk * 16;
            uint32_t afr[2][4], bfr[8][2];
            #pragma unroll
            for (int mi = 0; mi < 2; mi++)
                ldsm4(afr[mi], sptr(sa + (wm * 32 + mi * 16 + aRow) * ROWH + kc + aCol));
            #pragma unroll
            for (int u = 0; u < 4; u++) {
                uint32_t t[4];
                ldsm4(t, sptr(sb + (wn * 64 + u * 16 + bRow) * ROWH + kc + bCol));
                bfr[2 * u][0] = t[0]; bfr[2 * u][1] = t[1];
                bfr[2 * u + 1][0] = t[2]; bfr[2 * u + 1][1] = t[3];
            }
            #pragma unroll
            for (int mi = 0; mi < 2; mi++)
                #pragma unroll
                for (int ni = 0; ni < 8; ni++)
                    mma16816(acc[mi][ni], afr[mi], bfr[ni]);
        }
        __syncthreads();
    }

    // epilogue
    #pragma unroll
    for (int mi = 0; mi < 2; mi++) {
        long r0 = rowA0 + wm * 32 + mi * 16 + grp;
        #pragma unroll
        for (int ni = 0; ni < 8; ni++) {
            long c = rowB0 + wn * 64 + ni * 8 + tig * 2;
            float b0 = bias[c], b1 = bias[c + 1];
            float v00 = acc[mi][ni][0] + b0, v01 = acc[mi][ni][1] + b1;
            float v10 = acc[mi][ni][2] + b0, v11 = acc[mi][ni][3] + b1;
            if constexpr (sizeof(OutT) == 2) {
                *(uint32_t*)((__half*)C + r0 * N + c)       = packh2(v00, v01);
                *(uint32_t*)((__half*)C + (r0 + 8) * N + c) = packh2(v10, v11);
            } else {
                *(float2*)((float*)C + r0 * N + c)       = make_float2(v00, v01);
                *(float2*)((float*)C + (r0 + 8) * N + c) = make_float2(v10, v11);
            }
        }
    }
}

// ============================================================================
// tensor-core window attention: one block (128 thr, 4 warps) per (b, h)
// S = Q K^T (mma, M=64pad, N=56pad, K=32), softmax fp32 in regs, O = P V.
// ============================================================================
__global__ __launch_bounds__(128)
void attn_mma(const __half* __restrict__ qkv, const float* __restrict__ mask,
              const float* __restrict__ rpb, __half* __restrict__ obuf)
{
    __shared__ __half qs[64 * ROWH], ks[64 * ROWH], vs[64 * ROWH];
    __shared__ float masks[NTOK * NTOK];
    __shared__ float rpbs[169];

    const int h = blockIdx.x, b = blockIdx.y;
    const int tid  = threadIdx.x;
    const int wid  = tid >> 5, lane = tid & 31;
    const int grp  = lane >> 2, tig = lane & 3;

    // zero pads (full zero of the three tiles)
    for (int i = tid; i < 64 * ROWH / 2; i += 128) {
        ((uint32_t*)qs)[i] = 0; ((uint32_t*)ks)[i] = 0; ((uint32_t*)vs)[i] = 0;
    }
    __syncthreads();

    // fill q/k/v: 49 rows x 16 half2 each, straight half2 copies
    {
        const __half* base = qkv + (long)(b * NTOK) * (3 * DIMC) + h * HDIM;
        for (int idx = tid; idx < NTOK * 16; idx += 128) {
            int n = idx >> 4, d2 = (idx & 15) * 2;
            const __half* p = base + (long)n * (3 * DIMC) + d2;
            *(uint32_t*)(qs + n * ROWH + d2) = *(const uint32_t*)(p);
            *(uint32_t*)(ks + n * ROWH + d2) = *(const uint32_t*)(p + DIMC);
            *(uint32_t*)(vs + n * ROWH + d2) = *(const uint32_t*)(p + 2 * DIMC);
        }
        const int w = b & (NWIN - 1);
        const float* mp = mask + (long)w * NTOK * NTOK;
        for (int i = tid; i < NTOK * NTOK; i += 128) masks[i] = mp[i];
        for (int i = tid; i < 169; i += 128) rpbs[i] = rpb[i * NHEADS + h];
    }
    __syncthreads();

    // ---- S = Q K^T : warp wid owns rows [16*wid, 16*wid+16), 7 n8 tiles ----
    const int aRow = wid * 16 + ((lane >> 3) & 1) * 8 + (lane & 7);
    const int aCol = ((lane >> 4) & 1) * 8;
    const int bRow = ((lane >> 4) & 1) * 8 + (lane & 7);
    const int bCol = ((lane >> 3) & 1) * 8;

    float sacc[7][4];
    #pragma unroll
    for (int t = 0; t < 7; t++)
        #pragma unroll
        for (int e = 0; e < 4; e++) sacc[t][e] = 0.f;

    #pragma unroll
    for (int kk = 0; kk < 2; kk++) {
        const int kc = kk * 16;
        uint32_t a[4];
        ldsm4(a, sptr(qs + aRow * ROWH + kc + aCol));
        #pragma unroll
        for (int u = 0; u < 4; u++) {
            uint32_t t4[4];
            ldsm4(t4, sptr(ks + (u * 16 + bRow) * ROWH + kc + bCol));
            mma16816(sacc[2 * u], a, t4);
            if (2 * u + 1 < 7) mma16816(sacc[2 * u + 1], a, t4 + 2);
        }
    }

    // ---- scale + bias + mask, softmax (rows r0=i0, r1=i0+8) ----
    const int i0 = wid * 16 + grp;
    const int i1 = i0 + 8;
    const int ih0 = i0 / 7, iw0 = i0 - ih0 * 7;
    const int ih1 = i1 / 7, iw1 = i1 - ih1 * 7;

    #pragma unroll
    for (int t = 0; t < 7; t++) {
        #pragma unroll
        for (int e = 0; e < 4; e++) {
            int c = 8 * t + 2 * tig + (e & 1);
            int i = (e < 2) ? i0 : i1;
            float v = sacc[t][e] * QK_SCALE;
            if (c >= NTOK) v = -1e30f;
            else if (i < NTOK) {
                int ch = c / 7, cw = c - ch * 7;
                int ihh = (e < 2) ? ih0 : ih1, iww = (e < 2) ? iw0 : iw1;
                int ridx = (ihh - ch + 6) * 13 + (iww - cw + 6);
                v += rpbs[ridx] + masks[i * NTOK + c];
            }
            sacc[t][e] = v;
        }
    }

    float m0 = -1e30f, m1 = -1e30f;
    #pragma unroll
    for (int t = 0; t < 7; t++) {
        m0 = fmaxf(m0, fmaxf(sacc[t][0], sacc[t][1]));
        m1 = fmaxf(m1, fmaxf(sacc[t][2], sacc[t][3]));
    }
    m0 = fmaxf(m0, __shfl_xor_sync(0xffffffffu, m0, 1));
    m0 = fmaxf(m0, __shfl_xor_sync(0xffffffffu, m0, 2));
    m1 = fmaxf(m1, __shfl_xor_sync(0xffffffffu, m1, 1));
    m1 = fmaxf(m1, __shfl_xor_sync(0xffffffffu, m1, 2));

    float s0 = 0.f, s1 = 0.f;
    #pragma unroll
    for (int t = 0; t < 7; t++) {
        sacc[t][0] = __expf(sacc[t][0] - m0); s0 += sacc[t][0];
        sacc[t][1] = __expf(sacc[t][1] - m0); s0 += sacc[t][1];
        sacc[t][2] = __expf(sacc[t][2] - m1); s1 += sacc[t][2];
        sacc[t][3] = __expf(sacc[t][3] - m1); s1 += sacc[t][3];
    }
    s0 += __shfl_xor_sync(0xffffffffu, s0, 1);
    s0 += __shfl_xor_sync(0xffffffffu, s0, 2);
    s1 += __shfl_xor_sync(0xffffffffu, s1, 1);
    s1 += __shfl_xor_sync(0xffffffffu, s1, 2);
    const float inv0 = 1.f / s0, inv1 = 1.f / s1;

    // ---- pack P into A-fragments: 4 k16 chunks ----
    uint32_t pa[4][4];
    #pragma unroll
    for (int g = 0; g < 4; g++) {
        int t0 = 2 * g, t1 = 2 * g + 1;
        pa[g][0] = packh2(sacc[t0][0], sacc[t0][1]);
        pa[g][1] = packh2(sacc[t0][2], sacc[t0][3]);
        if (t1 < 7) {
            pa[g][2] = packh2(sacc[t1][0], sacc[t1][1]);
            pa[g][3] = packh2(sacc[t1][2], sacc[t1][3]);
        } else { pa[g][2] = 0; pa[g][3] = 0; }
    }

    // ---- O = P V : V via ldmatrix.trans, K=64(pad), N=32 ----
    float oacc[4][4];
    #pragma unroll
    for (int t = 0; t < 4; t++)
        #pragma unroll
        for (int e = 0; e < 4; e++) oacc[t][e] = 0.f;

    const int vRow = ((lane >> 3) & 1) * 8 + (lane & 7);
    const int vCol = ((lane >> 4) & 1) * 8;
    #pragma unroll
    for (int g = 0; g < 4; g++) {
        uint32_t v0[4], v1[4];
        ldsm4t(v0, sptr(vs + (g * 16 + vRow) * ROWH + 0  + vCol));
        ldsm4t(v1, sptr(vs + (g * 16 + vRow) * ROWH + 16 + vCol));
        mma16816(oacc[0], pa[g], v0);
        mma16816(oacc[1], pa[g], v0 + 2);
        mma16816(oacc[2], pa[g], v1);
        mma16816(oacc[3], pa[g], v1 + 2);
    }

    // ---- store (fp16, (m,512) layout) ----
    const long ob = (long)(b * NTOK) * DIMC + h * HDIM;
    #pragma unroll
    for (int t = 0; t < 4; t++) {
        int c = 8 * t + 2 * tig;
        if (i0 < NTOK)
            *(uint32_t*)(obuf + ob + (long)i0 * DIMC + c) =
                packh2(oacc[t][0] * inv0, oacc[t][1] * inv0);
        if (i1 < NTOK)
            *(uint32_t*)(obuf + ob + (long)i1 * DIMC + c) =
                packh2(oacc[t][2] * inv1, oacc[t][3] * inv1);
    }
}

// ---------------- launch ---------------------------------------------------
extern "C" void kernel_launch(void* const* d_in, const int* in_sizes, int n_in,
                              void* d_out, int out_size)
{
    const float* x      = (const float*)d_in[0];
    const float* mask   = (const float*)d_in[1];
    const float* qkv_w  = (const float*)d_in[2];
    const float* qkv_b  = (const float*)d_in[3];
    const float* proj_w = (const float*)d_in[4];
    const float* proj_b = (const float*)d_in[5];
    const float* rpb    = (const float*)d_in[6];
    float* out = (float*)d_out;

    __half *qkvh = nullptr, *obuf = nullptr, *xh = nullptr, *wqkv = nullptr, *wprj = nullptr;
    cudaGetSymbolAddress((void**)&qkvh, g_qkvh);
    cudaGetSymbolAddress((void**)&obuf, g_obuf);
    cudaGetSymbolAddress((void**)&xh,   g_xh);
    cudaGetSymbolAddress((void**)&wqkv, g_wqkv);
    cudaGetSymbolAddress((void**)&wprj, g_wprj);

    cudaFuncSetAttribute(gemm_hf<__half>, cudaFuncAttributeMaxDynamicSharedMemorySize, SMEM_GEMM);
    cudaFuncSetAttribute(gemm_hf<float>,  cudaFuncAttributeMaxDynamicSharedMemorySize, SMEM_GEMM);

    // 0) fp32 -> fp16 converts
    {
        long n4 = (long)M_TOT * DIMC / 4;
        f2h_kernel<<<(unsigned)((n4 + 255) / 256), 256>>>(x, xh, n4);
        long w4 = (long)3 * DIMC * DIMC / 4;
        f2h_kernel<<<(unsigned)((w4 + 255) / 256), 256>>>(qkv_w, wqkv, w4);
        long p4 = (long)DIMC * DIMC / 4;
        f2h_kernel<<<(unsigned)((p4 + 255) / 256), 256>>>(proj_w, wprj, p4);
    }

    // 1) qkv = x @ qkv_w^T + qkv_b   -> fp16 (M x 1536)
    dim3 g1(3 * DIMC / 128, M_TOT / 128);
    gemm_hf<__half><<<g1, 256, SMEM_GEMM>>>(xh, wqkv, qkv_b, qkvh, 3 * DIMC);

    // 2) tensor-core windowed attention -> fp16 (M x 512)
    attn_mma<<<dim3(NHEADS, BATCH), 128>>>(qkvh, mask, rpb, obuf);

    // 3) out = attn_out @ proj_w^T + proj_b   (M x 512) fp32
    dim3 g2(DIMC / 128, M_TOT / 128);
    gemm_hf<float><<<g2, 256, SMEM_GEMM>>>(obuf, wprj, proj_b, out, DIMC);
}